// round 11
// baseline (speedup 1.0000x reference)
#include <cuda_runtime.h>
#include <cuda_bf16.h>
#include <math.h>

// Problem constants
#define B      32
#define CIN    512
#define HW     4096          // 64*64
#define MID    32            // 512/16
#define COUT   512

#define POOL_CTAS    (B * CIN)            // 16384
#define FC_PER_BATCH 4
#define FC_CTAS      (B * FC_PER_BATCH)   // 128
#define GRID_CTAS    (POOL_CTAS + FC_CTAS)

// Scratch (no cudaMalloc allowed)
__device__ float        g_pooled[B * CIN];  // [B, CIN] means
__device__ unsigned int g_arrive;           // zero-init; reset each replay
__device__ unsigned int g_done;             // zero-init; reset each replay

__device__ __forceinline__ void l2_prefetch(const void* p) {
    asm volatile("prefetch.global.L2 [%0];" :: "l"(p));
}

// ---------------------------------------------------------------------------
// Single fused kernel.
//  blockIdx < POOL_CTAS : pool one (b,c) row (byte-identical to the proven
//    6.9 TB/s kernel), publish mean, fence, arrive.
//  blockIdx >= POOL_CTAS: FC CTA f = blockIdx - POOL_CTAS; batch b = f/4,
//    output quarter q = f%4 (outputs [128q, 128q+128)).
//    1) L2-prefetch w1 (all) + its w2 quarter  (overlaps with pool tail)
//    2) spin on g_arrive == POOL_CTAS (acquire)
//    3) phase 1: 8 warps x 4 mids -> s_h (ReLU)
//    4) phase 2: warp w computes 16 outputs via coalesced w2 loads (L2-hot)
//       + butterfly reduces; lanes 0..15 store sigmoid results.
//    5) last FC CTA resets counters (replay-deterministic).
// Tiny smem / no big tiles -> zero occupancy tax on the pool phase (R5 fix).
// ---------------------------------------------------------------------------
__global__ __launch_bounds__(256) void se_onekernel(
    const float* __restrict__ x,
    const float* __restrict__ w1, const float* __restrict__ b1,
    const float* __restrict__ w2, const float* __restrict__ b2,
    float* __restrict__ out)
{
    const int tid  = threadIdx.x;
    const int lane = tid & 31;
    const int wid  = tid >> 5;

    if (blockIdx.x < POOL_CTAS) {
        // ---------------- Pool path (unchanged math) ----------------
        const int row = blockIdx.x;
        const float4* __restrict__ p =
            reinterpret_cast<const float4*>(x + (size_t)row * HW);

        float4 v0 = p[tid];
        float4 v1 = p[tid + 256];
        float4 v2 = p[tid + 512];
        float4 v3 = p[tid + 768];

        float s = (v0.x + v0.y) + (v0.z + v0.w)
                + (v1.x + v1.y) + (v1.z + v1.w)
                + (v2.x + v2.y) + (v2.z + v2.w)
                + (v3.x + v3.y) + (v3.z + v3.w);

        #pragma unroll
        for (int off = 16; off > 0; off >>= 1)
            s += __shfl_xor_sync(0xFFFFFFFFu, s, off);

        __shared__ float warp_sums[8];
        if (lane == 0) warp_sums[wid] = s;
        __syncthreads();

        if (wid == 0) {
            float t = (lane < 8) ? warp_sums[lane] : 0.0f;
            #pragma unroll
            for (int off = 4; off > 0; off >>= 1)
                t += __shfl_xor_sync(0xFFFFFFFFu, t, off);
            if (lane == 0) {
                g_pooled[row] = t * (1.0f / (float)HW);
                __threadfence();                   // release mean
                atomicAdd(&g_arrive, 1u);          // arrive
            }
        }
        return;
    }

    // ---------------- FC path ----------------
    const int f = blockIdx.x - POOL_CTAS;   // 0..127
    const int b = f >> 2;                   // batch
    const int q = f & 3;                    // output quarter
    const int obase_cta = q * 128;          // outputs [obase_cta, +128)

    __shared__ float s_pooled[CIN];
    __shared__ float s_h[MID];

    // 1) L2 prefetch of weights (independent of pool results).
    //    w1: 64 KB = 512 lines; thread t prefetches lines t and t+256.
    l2_prefetch(w1 + tid * 32);
    l2_prefetch(w1 + (tid + 256) * 32);
    //    w2 quarter: 128 rows x 128 B; thread t<128 prefetches row obase+t.
    if (tid < 128) l2_prefetch(w2 + (size_t)(obase_cta + tid) * MID);
    if (tid == 0) { l2_prefetch(b1); l2_prefetch(b2 + obase_cta); }

    // 2) Spin until all pool CTAs arrived (acquire).
    if (tid == 0) {
        while (atomicAdd(&g_arrive, 0u) < (unsigned)POOL_CTAS)
            __nanosleep(64);
        __threadfence();
    }
    __syncthreads();

    s_pooled[tid]       = g_pooled[b * CIN + tid];
    s_pooled[tid + 256] = g_pooled[b * CIN + tid + 256];
    __syncthreads();

    // 3) Phase 1: warp wid computes mids {4*wid .. 4*wid+3}
    {
        const int m0 = wid * 4;
        const float* __restrict__ w1r0 = w1 + (size_t)(m0 + 0) * CIN;
        const float* __restrict__ w1r1 = w1 + (size_t)(m0 + 1) * CIN;
        const float* __restrict__ w1r2 = w1 + (size_t)(m0 + 2) * CIN;
        const float* __restrict__ w1r3 = w1 + (size_t)(m0 + 3) * CIN;

        float a0 = 0.f, a1 = 0.f, a2 = 0.f, a3 = 0.f;
        #pragma unroll
        for (int j = 0; j < 16; j++) {
            const int k = lane + 32 * j;
            const float pv = s_pooled[k];
            a0 = fmaf(pv, w1r0[k], a0);
            a1 = fmaf(pv, w1r1[k], a1);
            a2 = fmaf(pv, w1r2[k], a2);
            a3 = fmaf(pv, w1r3[k], a3);
        }
        #pragma unroll
        for (int off = 16; off > 0; off >>= 1) {
            a0 += __shfl_xor_sync(0xFFFFFFFFu, a0, off);
            a1 += __shfl_xor_sync(0xFFFFFFFFu, a1, off);
            a2 += __shfl_xor_sync(0xFFFFFFFFu, a2, off);
            a3 += __shfl_xor_sync(0xFFFFFFFFu, a3, off);
        }
        if (lane == 0) {
            float h0 = a0 + b1[m0 + 0];
            float h1 = a1 + b1[m0 + 1];
            float h2 = a2 + b1[m0 + 2];
            float h3 = a3 + b1[m0 + 3];
            s_h[m0 + 0] = h0 > 0.f ? h0 : 0.f;
            s_h[m0 + 1] = h1 > 0.f ? h1 : 0.f;
            s_h[m0 + 2] = h2 > 0.f ? h2 : 0.f;
            s_h[m0 + 3] = h3 > 0.f ? h3 : 0.f;
        }
    }
    __syncthreads();

    // 4) Phase 2: warp wid owns 16 outputs [obase_cta + 16*wid, +16).
    {
        const int obase = obase_cta + wid * 16;
        const float hv  = s_h[lane];
        float res = 0.0f;

        #pragma unroll
        for (int i = 0; i < 16; i++) {
            float r = w2[(size_t)(obase + i) * MID + lane];   // coalesced, L2-hot
            float p = r * hv;
            #pragma unroll
            for (int off = 16; off > 0; off >>= 1)
                p += __shfl_xor_sync(0xFFFFFFFFu, p, off);
            if (lane == i) res = p;            // lane i (i<16) keeps output
        }

        if (lane < 16) {
            const int o = obase + lane;
            float acc = res + b2[o];
            out[(size_t)b * COUT + o] = 1.0f / (1.0f + __expf(-acc));
        }
    }
    __syncthreads();

    // 5) Reset counters for next graph replay (last FC CTA).
    if (tid == 0) {
        unsigned d = atomicAdd(&g_done, 1u);
        if (d == (unsigned)(FC_CTAS - 1)) {
            g_arrive = 0u;
            g_done   = 0u;
            __threadfence();
        }
    }
}

// ---------------------------------------------------------------------------
extern "C" void kernel_launch(void* const* d_in, const int* in_sizes, int n_in,
                              void* d_out, int out_size) {
    const float* x  = (const float*)d_in[0];
    const float* w1 = (const float*)d_in[1];
    const float* b1 = (const float*)d_in[2];
    const float* w2 = (const float*)d_in[3];
    const float* b2 = (const float*)d_in[4];
    float* out = (float*)d_out;

    se_onekernel<<<GRID_CTAS, 256>>>(x, w1, b1, w2, b2, out);
}

// round 12
// speedup vs baseline: 1.0285x; 1.0285x over previous
#include <cuda_runtime.h>
#include <cuda_bf16.h>
#include <math.h>

// Problem constants
#define B      32
#define CIN    512
#define HW     4096          // 64*64
#define MID    32            // 512/16
#define COUT   512

#define FC_CTAS    B                    // 32, blockIdx 0..31 (scheduled in wave 1)
#define POOL_CTAS  (B * CIN)            // 16384, blockIdx 32..16415
#define GRID_CTAS  (FC_CTAS + POOL_CTAS)
#define CNT_PAD    32                   // 32 uints = 128B -> one L2 line per counter

// Scratch (no cudaMalloc allowed)
__device__ float        g_pooled[B * CIN];      // [B, CIN] means
__device__ unsigned int g_cnt[B * CNT_PAD];     // per-batch arrive counters (padded)

__device__ __forceinline__ void l2_prefetch(const void* p) {
    asm volatile("prefetch.global.L2 [%0];" :: "l"(p));
}

// ---------------------------------------------------------------------------
// Fused kernel, v3 (contention-free handoff).
//  blockIdx >= FC_CTAS: pool row (blockIdx-32): identical 6.9 TB/s reduction;
//    writer thread stores mean, __threadfence (release), RED.ADD on its
//    batch's private counter (128B-isolated line).
//  blockIdx < FC_CTAS: FC CTA for batch b = blockIdx:
//    - L2-prefetch w1 + w2 (re-warmed by each FC CTA; negligible traffic)
//    - tid0 spins on a volatile LOAD of g_cnt[b] (no RMW, no serialization)
//      until 512 rows of batch b arrived; resets counter (safe: final value).
//    - phase 1: 8 warps x 4 mids (coalesced hot-L2 w1 reads, butterflies)
//    - phase 2: 8 warps x 64 outputs (coalesced hot-L2 w2 reads, butterflies)
//  <=32 regs (launch_bounds 256,8) + ~2.3KB smem -> zero pool occupancy tax.
// ---------------------------------------------------------------------------
__global__ __launch_bounds__(256, 8) void se_onekernel(
    const float* __restrict__ x,
    const float* __restrict__ w1, const float* __restrict__ b1,
    const float* __restrict__ w2, const float* __restrict__ b2,
    float* __restrict__ out)
{
    const int tid  = threadIdx.x;
    const int lane = tid & 31;
    const int wid  = tid >> 5;

    __shared__ float warp_sums[8];
    __shared__ float s_pooled[CIN];
    __shared__ float s_h[MID];

    if (blockIdx.x >= FC_CTAS) {
        // ---------------- Pool path (unchanged math, 6.9 TB/s) ----------------
        const int row = blockIdx.x - FC_CTAS;      // 0..16383; batch = row>>9
        const float4* __restrict__ p =
            reinterpret_cast<const float4*>(x + (size_t)row * HW);

        float4 v0 = p[tid];
        float4 v1 = p[tid + 256];
        float4 v2 = p[tid + 512];
        float4 v3 = p[tid + 768];

        float s = (v0.x + v0.y) + (v0.z + v0.w)
                + (v1.x + v1.y) + (v1.z + v1.w)
                + (v2.x + v2.y) + (v2.z + v2.w)
                + (v3.x + v3.y) + (v3.z + v3.w);

        #pragma unroll
        for (int off = 16; off > 0; off >>= 1)
            s += __shfl_xor_sync(0xFFFFFFFFu, s, off);

        if (lane == 0) warp_sums[wid] = s;
        __syncthreads();

        if (wid == 0) {
            float t = (lane < 8) ? warp_sums[lane] : 0.0f;
            #pragma unroll
            for (int off = 4; off > 0; off >>= 1)
                t += __shfl_xor_sync(0xFFFFFFFFu, t, off);
            if (lane == 0) {
                g_pooled[row] = t * (1.0f / (float)HW);
                __threadfence();                       // release the mean
                atomicAdd(&g_cnt[(row >> 9) * CNT_PAD], 1u);   // RED.ADD arrive
            }
        }
        return;
    }

    // ---------------- FC path: batch b = blockIdx.x ----------------
    const int b = blockIdx.x;

    // Prefetch weights into L2 (each FC CTA re-warms them; 128KB total).
    l2_prefetch(w1 + (tid)       * 32);
    l2_prefetch(w1 + (tid + 256) * 32);
    l2_prefetch(w2 + (tid)       * 32);
    l2_prefetch(w2 + (tid + 256) * 32);
    if (tid == 0) { l2_prefetch(b1); l2_prefetch(b2); l2_prefetch(b2 + 256); }

    // Spin (volatile LOAD — no atomic RMW contention) until batch b complete.
    if (tid == 0) {
        volatile unsigned int* cnt = &g_cnt[b * CNT_PAD];
        while (*cnt < (unsigned)CIN)
            __nanosleep(64);
        *cnt = 0u;                                 // reset for next replay
        __threadfence();                           // acquire
    }
    __syncthreads();

    // Load this batch's pooled row (L2-fresh; bypass L1).
    s_pooled[tid]       = __ldcg(&g_pooled[b * CIN + tid]);
    s_pooled[tid + 256] = __ldcg(&g_pooled[b * CIN + tid + 256]);
    __syncthreads();

    // Phase 1: warp wid computes mids {4*wid .. 4*wid+3}
    {
        const int m0 = wid * 4;
        const float* __restrict__ w1r0 = w1 + (size_t)(m0 + 0) * CIN;
        const float* __restrict__ w1r1 = w1 + (size_t)(m0 + 1) * CIN;
        const float* __restrict__ w1r2 = w1 + (size_t)(m0 + 2) * CIN;
        const float* __restrict__ w1r3 = w1 + (size_t)(m0 + 3) * CIN;

        float a0 = 0.f, a1 = 0.f, a2 = 0.f, a3 = 0.f;
        #pragma unroll
        for (int j = 0; j < 16; j++) {
            const int k = lane + 32 * j;
            const float pv = s_pooled[k];
            a0 = fmaf(pv, __ldg(w1r0 + k), a0);
            a1 = fmaf(pv, __ldg(w1r1 + k), a1);
            a2 = fmaf(pv, __ldg(w1r2 + k), a2);
            a3 = fmaf(pv, __ldg(w1r3 + k), a3);
        }
        #pragma unroll
        for (int off = 16; off > 0; off >>= 1) {
            a0 += __shfl_xor_sync(0xFFFFFFFFu, a0, off);
            a1 += __shfl_xor_sync(0xFFFFFFFFu, a1, off);
            a2 += __shfl_xor_sync(0xFFFFFFFFu, a2, off);
            a3 += __shfl_xor_sync(0xFFFFFFFFu, a3, off);
        }
        if (lane == 0) {
            float h0 = a0 + __ldg(b1 + m0 + 0);
            float h1 = a1 + __ldg(b1 + m0 + 1);
            float h2 = a2 + __ldg(b1 + m0 + 2);
            float h3 = a3 + __ldg(b1 + m0 + 3);
            s_h[m0 + 0] = h0 > 0.f ? h0 : 0.f;
            s_h[m0 + 1] = h1 > 0.f ? h1 : 0.f;
            s_h[m0 + 2] = h2 > 0.f ? h2 : 0.f;
            s_h[m0 + 3] = h3 > 0.f ? h3 : 0.f;
        }
    }
    __syncthreads();

    // Phase 2: warp wid owns outputs [64*wid, 64*wid+64).
    {
        const int obase = wid * 64;
        const float hv  = s_h[lane];
        float res0 = 0.0f, res1 = 0.0f;

        #pragma unroll
        for (int i = 0; i < 32; i++) {
            float r0 = __ldg(&w2[(size_t)(obase + i)      * MID + lane]);
            float r1 = __ldg(&w2[(size_t)(obase + 32 + i) * MID + lane]);
            float p0 = r0 * hv;
            float p1 = r1 * hv;
            #pragma unroll
            for (int off = 16; off > 0; off >>= 1) {
                p0 += __shfl_xor_sync(0xFFFFFFFFu, p0, off);
                p1 += __shfl_xor_sync(0xFFFFFFFFu, p1, off);
            }
            if (lane == i) { res0 = p0; res1 = p1; }
        }

        const int o0 = obase + lane;
        const int o1 = obase + 32 + lane;
        float acc0 = res0 + __ldg(b2 + o0);
        float acc1 = res1 + __ldg(b2 + o1);
        out[(size_t)b * COUT + o0] = 1.0f / (1.0f + __expf(-acc0));
        out[(size_t)b * COUT + o1] = 1.0f / (1.0f + __expf(-acc1));
    }
}

// ---------------------------------------------------------------------------
extern "C" void kernel_launch(void* const* d_in, const int* in_sizes, int n_in,
                              void* d_out, int out_size) {
    const float* x  = (const float*)d_in[0];
    const float* w1 = (const float*)d_in[1];
    const float* b1 = (const float*)d_in[2];
    const float* w2 = (const float*)d_in[3];
    const float* b2 = (const float*)d_in[4];
    float* out = (float*)d_out;

    se_onekernel<<<GRID_CTAS, 256>>>(x, w1, b1, w2, b2, out);
}

// round 14
// speedup vs baseline: 1.0846x; 1.0545x over previous
#include <cuda_runtime.h>
#include <cuda_bf16.h>
#include <math.h>

// Problem constants
#define B      32
#define CIN    512
#define HW     4096          // 64*64
#define MID    32            // 512/16
#define COUT   512

#define FC_CTAS    B                    // 32, blockIdx 0..31 (wave-1 resident)
#define POOL_CTAS  (B * CIN)            // 16384, blockIdx 32..16415
#define GRID_CTAS  (FC_CTAS + POOL_CTAS)
#define CNT_PAD    32                   // 128B per counter -> private L2 line

// Scratch (no cudaMalloc allowed)
__device__ float        g_pooled[B * CIN];      // [B, CIN] means
__device__ unsigned int g_cnt[B * CNT_PAD];     // per-batch arrive counters

__device__ __forceinline__ void l2_prefetch(const void* p) {
    asm volatile("prefetch.global.L2 [%0];" :: "l"(p));
}
// Release arrive: ordering rides on the RED op — NO membar, NO CCTL.IVALL.
__device__ __forceinline__ void red_add_release(unsigned int* p) {
    asm volatile("red.release.gpu.global.add.u32 [%0], 1;" :: "l"(p) : "memory");
}
// Acquire poll.
__device__ __forceinline__ unsigned int ld_acquire(const unsigned int* p) {
    unsigned int v;
    asm volatile("ld.acquire.gpu.global.u32 %0, [%1];" : "=r"(v) : "l"(p) : "memory");
    return v;
}

// ---------------------------------------------------------------------------
// Fused kernel, v4: v3 handoff + fence-free release/acquire protocol.
//  Pool CTAs (blockIdx>=32): identical 6.9 TB/s reduction; writer stores the
//    mean then red.release-arrives on its batch's private counter.
//  FC CTAs (blockIdx<32, batch b): L2-prefetch weights, acquire-poll counter
//    to 512, reset it, then phase1 (8 warps x 4 mids) + phase2 (8 warps x 64
//    outputs, coalesced hot-L2 w2 + butterflies), sigmoid, store.
// ---------------------------------------------------------------------------
__global__ __launch_bounds__(256, 8) void se_onekernel(
    const float* __restrict__ x,
    const float* __restrict__ w1, const float* __restrict__ b1,
    const float* __restrict__ w2, const float* __restrict__ b2,
    float* __restrict__ out)
{
    const int tid  = threadIdx.x;
    const int lane = tid & 31;
    const int wid  = tid >> 5;

    __shared__ float warp_sums[8];
    __shared__ float s_pooled[CIN];
    __shared__ float s_h[MID];

    if (blockIdx.x >= FC_CTAS) {
        // ---------------- Pool path (unchanged math, 6.9 TB/s) ----------------
        const int row = blockIdx.x - FC_CTAS;      // 0..16383; batch = row>>9
        const float4* __restrict__ p =
            reinterpret_cast<const float4*>(x + (size_t)row * HW);

        float4 v0 = p[tid];
        float4 v1 = p[tid + 256];
        float4 v2 = p[tid + 512];
        float4 v3 = p[tid + 768];

        float s = (v0.x + v0.y) + (v0.z + v0.w)
                + (v1.x + v1.y) + (v1.z + v1.w)
                + (v2.x + v2.y) + (v2.z + v2.w)
                + (v3.x + v3.y) + (v3.z + v3.w);

        #pragma unroll
        for (int off = 16; off > 0; off >>= 1)
            s += __shfl_xor_sync(0xFFFFFFFFu, s, off);

        if (lane == 0) warp_sums[wid] = s;
        __syncthreads();

        if (wid == 0) {
            float t = (lane < 8) ? warp_sums[lane] : 0.0f;
            #pragma unroll
            for (int off = 4; off > 0; off >>= 1)
                t += __shfl_xor_sync(0xFFFFFFFFu, t, off);
            if (lane == 0) {
                g_pooled[row] = t * (1.0f / (float)HW);
                red_add_release(&g_cnt[(row >> 9) * CNT_PAD]);  // fence-free arrive
            }
        }
        return;
    }

    // ---------------- FC path: batch b = blockIdx.x ----------------
    const int b = blockIdx.x;

    // Warm L2 with the weights while pool streams (128KB total, re-warmed).
    l2_prefetch(w1 + (tid)       * 32);
    l2_prefetch(w1 + (tid + 256) * 32);
    l2_prefetch(w2 + (tid)       * 32);
    l2_prefetch(w2 + (tid + 256) * 32);
    if (tid == 0) { l2_prefetch(b1); l2_prefetch(b2); l2_prefetch(b2 + 256); }

    // Acquire-poll until all 512 rows of batch b arrived; reset for replay.
    if (tid == 0) {
        unsigned int* cnt = &g_cnt[b * CNT_PAD];
        while (ld_acquire(cnt) < (unsigned)CIN)
            __nanosleep(64);
        *cnt = 0u;                                 // safe: all arrivals landed
    }
    __syncthreads();

    // Load this batch's pooled row (L2, bypass L1).
    s_pooled[tid]       = __ldcg(&g_pooled[b * CIN + tid]);
    s_pooled[tid + 256] = __ldcg(&g_pooled[b * CIN + tid + 256]);
    __syncthreads();

    // Phase 1: warp wid computes mids {4*wid .. 4*wid+3}
    {
        const int m0 = wid * 4;
        const float* __restrict__ w1r0 = w1 + (size_t)(m0 + 0) * CIN;
        const float* __restrict__ w1r1 = w1 + (size_t)(m0 + 1) * CIN;
        const float* __restrict__ w1r2 = w1 + (size_t)(m0 + 2) * CIN;
        const float* __restrict__ w1r3 = w1 + (size_t)(m0 + 3) * CIN;

        float a0 = 0.f, a1 = 0.f, a2 = 0.f, a3 = 0.f;
        #pragma unroll
        for (int j = 0; j < 16; j++) {
            const int k = lane + 32 * j;
            const float pv = s_pooled[k];
            a0 = fmaf(pv, __ldg(w1r0 + k), a0);
            a1 = fmaf(pv, __ldg(w1r1 + k), a1);
            a2 = fmaf(pv, __ldg(w1r2 + k), a2);
            a3 = fmaf(pv, __ldg(w1r3 + k), a3);
        }
        #pragma unroll
        for (int off = 16; off > 0; off >>= 1) {
            a0 += __shfl_xor_sync(0xFFFFFFFFu, a0, off);
            a1 += __shfl_xor_sync(0xFFFFFFFFu, a1, off);
            a2 += __shfl_xor_sync(0xFFFFFFFFu, a2, off);
            a3 += __shfl_xor_sync(0xFFFFFFFFu, a3, off);
        }
        if (lane == 0) {
            float h0 = a0 + __ldg(b1 + m0 + 0);
            float h1 = a1 + __ldg(b1 + m0 + 1);
            float h2 = a2 + __ldg(b1 + m0 + 2);
            float h3 = a3 + __ldg(b1 + m0 + 3);
            s_h[m0 + 0] = h0 > 0.f ? h0 : 0.f;
            s_h[m0 + 1] = h1 > 0.f ? h1 : 0.f;
            s_h[m0 + 2] = h2 > 0.f ? h2 : 0.f;
            s_h[m0 + 3] = h3 > 0.f ? h3 : 0.f;
        }
    }
    __syncthreads();

    // Phase 2: warp wid owns outputs [64*wid, 64*wid+64).
    {
        const int obase = wid * 64;
        const float hv  = s_h[lane];
        float res0 = 0.0f, res1 = 0.0f;

        #pragma unroll
        for (int i = 0; i < 32; i++) {
            float r0 = __ldg(&w2[(size_t)(obase + i)      * MID + lane]);
            float r1 = __ldg(&w2[(size_t)(obase + 32 + i) * MID + lane]);
            float p0 = r0 * hv;
            float p1 = r1 * hv;
            #pragma unroll
            for (int off = 16; off > 0; off >>= 1) {
                p0 += __shfl_xor_sync(0xFFFFFFFFu, p0, off);
                p1 += __shfl_xor_sync(0xFFFFFFFFu, p1, off);
            }
            if (lane == i) { res0 = p0; res1 = p1; }
        }

        const int o0 = obase + lane;
        const int o1 = obase + 32 + lane;
        float acc0 = res0 + __ldg(b2 + o0);
        float acc1 = res1 + __ldg(b2 + o1);
        out[(size_t)b * COUT + o0] = 1.0f / (1.0f + __expf(-acc0));
        out[(size_t)b * COUT + o1] = 1.0f / (1.0f + __expf(-acc1));
    }
}

// ---------------------------------------------------------------------------
extern "C" void kernel_launch(void* const* d_in, const int* in_sizes, int n_in,
                              void* d_out, int out_size) {
    const float* x  = (const float*)d_in[0];
    const float* w1 = (const float*)d_in[1];
    const float* b1 = (const float*)d_in[2];
    const float* w2 = (const float*)d_in[3];
    const float* b2 = (const float*)d_in[4];
    float* out = (float*)d_out;

    se_onekernel<<<GRID_CTAS, 256>>>(x, w1, b1, w2, b2, out);
}